// round 2
// baseline (speedup 1.0000x reference)
#include <cuda_runtime.h>

#define S_LEN 8192
#define DIN   512
#define DOUTC 64
#define NSPLIT 4
#define SPLIT_KEYS (S_LEN / NSPLIT)   // 2048
#define BM 64
#define BN 64
#define SCALE 0.125f                  // 1/sqrt(64)

// ---------------- scratch (device globals; no allocations allowed) ----------
__device__ float g_Q[S_LEN * DOUTC];
__device__ float g_K[S_LEN * DOUTC];
__device__ float g_V[S_LEN * DOUTC];
__device__ float g_Opart[NSPLIT * S_LEN * DOUTC];
__device__ float g_Mpart[NSPLIT * S_LEN];
__device__ float g_Lpart[NSPLIT * S_LEN];

// ---------------- QKV projection: out = x @ W^T -----------------------------
// grid (128, 3), block 256.  64x64 output tile per block, BK=32.
__global__ __launch_bounds__(256) void qkv_gemm_kernel(
    const float* __restrict__ x, const float* __restrict__ Wq,
    const float* __restrict__ Wk, const float* __restrict__ Wv) {
  __shared__ float xs[BM * 32];   // [m][k] natural
  __shared__ float ws[32 * 64];   // [k][n] transposed, rotation-swizzled
  const float* W  = (blockIdx.y == 0) ? Wq : (blockIdx.y == 1) ? Wk : Wv;
  float* out      = (blockIdx.y == 0) ? g_Q : (blockIdx.y == 1) ? g_K : g_V;
  const int tid = threadIdx.x;
  const int tx = tid & 15, ty = tid >> 4;
  const int mb = blockIdx.x * BM;
  const int kl = tid & 31, r0 = tid >> 5;

  float acc[4][4] = {};

  for (int kt = 0; kt < DIN; kt += 32) {
    __syncthreads();
#pragma unroll
    for (int r = 0; r < 8; r++) {
      int m = r0 * 8 + r;                 // 0..63
      xs[m * 32 + kl] = x[(mb + m) * DIN + kt + kl];
      // transposed store with 4-aligned rotation: conflict degree 32 -> 4
      ws[kl * 64 + ((m + 4 * (kl & 15)) & 63)] = W[m * DIN + kt + kl];
    }
    __syncthreads();
#pragma unroll 16
    for (int kk = 0; kk < 32; kk++) {
      float4 b = *(const float4*)&ws[kk * 64 + ((4 * tx + 4 * (kk & 15)) & 63)];
      float a[4];
#pragma unroll
      for (int i = 0; i < 4; i++) a[i] = xs[(ty * 4 + i) * 32 + kk];
#pragma unroll
      for (int i = 0; i < 4; i++) {
        acc[i][0] = fmaf(a[i], b.x, acc[i][0]);
        acc[i][1] = fmaf(a[i], b.y, acc[i][1]);
        acc[i][2] = fmaf(a[i], b.z, acc[i][2]);
        acc[i][3] = fmaf(a[i], b.w, acc[i][3]);
      }
    }
  }
#pragma unroll
  for (int i = 0; i < 4; i++) {
    *(float4*)&out[(mb + ty * 4 + i) * DOUTC + tx * 4] =
        make_float4(acc[i][0], acc[i][1], acc[i][2], acc[i][3]);
  }
}

// ---------------- flash attention, split-KV ----------------------------------
// grid (128 row-blocks, NSPLIT splits), block 256.
// Thread (tx,ty) owns rows {4*ty+i}, cols {4*tx+j}.
__global__ __launch_bounds__(256) void attn_kernel() {
  __shared__ float qs[BM * 64];    // Q [m][d] natural
  __shared__ float kv[BN * 64];    // K phase: [d][n] rotated; V phase: [n][d] natural
  __shared__ float ps[BM * BN];    // P [m][key] natural
  const int tid = threadIdx.x;
  const int tx = tid & 15, ty = tid >> 4;
  const int row0 = blockIdx.x * BM;
  const int sp = blockIdx.y;
  const int qmax = row0 + BM - 1;
  const int k0 = sp * SPLIT_KEYS;

  if (k0 > qmax) {   // split entirely in the masked future: sentinel partials
    if (tid < BM) {
      g_Mpart[sp * S_LEN + row0 + tid] = -1e30f;
      g_Lpart[sp * S_LEN + row0 + tid] = 0.0f;
    }
    return;
  }
  const int kend = min(k0 + SPLIT_KEYS, qmax + 1);  // always multiple of 64

  // load Q tile (straight float4 copy)
  {
    float4* dst = (float4*)qs;
    const float4* src = (const float4*)&g_Q[row0 * DOUTC];
#pragma unroll
    for (int i = 0; i < 4; i++) dst[tid + 256 * i] = src[tid + 256 * i];
  }

  float acc[4][4] = {};
  float mrow[4], lrow[4];
#pragma unroll
  for (int i = 0; i < 4; i++) { mrow[i] = -1e30f; lrow[i] = 0.0f; }

  const int dcol = tid & 63, nr0 = tid >> 6;  // for K transpose load

  for (int kb = k0; kb < kend; kb += BN) {
    __syncthreads();   // kv (V of prev iter) and ps fully consumed
    // K tile: transposed [d][n] with 4-aligned rotation (conflict-free STS)
#pragma unroll
    for (int r = 0; r < 16; r++) {
      int n = nr0 * 16 + r;
      kv[dcol * 64 + ((n + 4 * (dcol & 15)) & 63)] = g_K[(kb + n) * DOUTC + dcol];
    }
    __syncthreads();

    // ---- S = Q @ K^T  (reduction over d) ----
    float c[4][4] = {};
#pragma unroll 16
    for (int d = 0; d < 64; d++) {
      float4 b = *(const float4*)&kv[d * 64 + ((4 * tx + 4 * (d & 15)) & 63)];
      float a[4];
#pragma unroll
      for (int i = 0; i < 4; i++) a[i] = qs[(ty * 4 + i) * 64 + d];
#pragma unroll
      for (int i = 0; i < 4; i++) {
        c[i][0] = fmaf(a[i], b.x, c[i][0]);
        c[i][1] = fmaf(a[i], b.y, c[i][1]);
        c[i][2] = fmaf(a[i], b.z, c[i][2]);
        c[i][3] = fmaf(a[i], b.w, c[i][3]);
      }
    }

    // ---- online softmax (rows live in 16-lane half-warps) ----
#pragma unroll
    for (int i = 0; i < 4; i++) {
      const int mg = row0 + ty * 4 + i;
      float s[4];
#pragma unroll
      for (int j = 0; j < 4; j++) {
        s[j] = c[i][j] * SCALE;
        if (kb + tx * 4 + j > mg) s[j] = -1e30f;   // causal mask
      }
      float tmax = fmaxf(fmaxf(s[0], s[1]), fmaxf(s[2], s[3]));
#pragma unroll
      for (int off = 8; off >= 1; off >>= 1)
        tmax = fmaxf(tmax, __shfl_xor_sync(0xffffffffu, tmax, off));
      const float mnew = fmaxf(mrow[i], tmax);
      const float corr = __expf(mrow[i] - mnew);
      const float p0 = __expf(s[0] - mnew);
      const float p1 = __expf(s[1] - mnew);
      const float p2 = __expf(s[2] - mnew);
      const float p3 = __expf(s[3] - mnew);
      float rs = (p0 + p1) + (p2 + p3);
#pragma unroll
      for (int off = 8; off >= 1; off >>= 1)
        rs += __shfl_xor_sync(0xffffffffu, rs, off);
      lrow[i] = lrow[i] * corr + rs;
      mrow[i] = mnew;
#pragma unroll
      for (int j = 0; j < 4; j++) acc[i][j] *= corr;
      *(float4*)&ps[(ty * 4 + i) * BN + tx * 4] = make_float4(p0, p1, p2, p3);
    }
    __syncthreads();   // ps visible; kv(K) fully consumed

    // V tile: natural [n][d] (straight float4 copy into same buffer)
    {
      float4* dst = (float4*)kv;
      const float4* src = (const float4*)&g_V[kb * DOUTC];
#pragma unroll
      for (int i = 0; i < 4; i++) dst[tid + 256 * i] = src[tid + 256 * i];
    }
    __syncthreads();

    // ---- O += P @ V  (reduction over keys) ----
#pragma unroll 16
    for (int kk = 0; kk < 64; kk++) {
      float4 b = *(const float4*)&kv[kk * 64 + tx * 4];
      float a[4];
#pragma unroll
      for (int i = 0; i < 4; i++) a[i] = ps[(ty * 4 + i) * BN + kk];
#pragma unroll
      for (int i = 0; i < 4; i++) {
        acc[i][0] = fmaf(a[i], b.x, acc[i][0]);
        acc[i][1] = fmaf(a[i], b.y, acc[i][1]);
        acc[i][2] = fmaf(a[i], b.z, acc[i][2]);
        acc[i][3] = fmaf(a[i], b.w, acc[i][3]);
      }
    }
  }

  // ---- write split partials (unnormalized acc + row stats) ----
#pragma unroll
  for (int i = 0; i < 4; i++) {
    const int row = row0 + ty * 4 + i;
    *(float4*)&g_Opart[(sp * S_LEN + row) * DOUTC + tx * 4] =
        make_float4(acc[i][0], acc[i][1], acc[i][2], acc[i][3]);
    if (tx == 0) {
      g_Mpart[sp * S_LEN + row] = mrow[i];
      g_Lpart[sp * S_LEN + row] = lrow[i];
    }
  }
}

// ---------------- combine split partials -------------------------------------
__global__ __launch_bounds__(256) void combine_kernel(float* __restrict__ out) {
  const int idx = blockIdx.x * 256 + threadIdx.x;   // < S_LEN * DOUTC
  const int row = idx >> 6;
  const int d = idx & 63;
  float M = -1e30f;
#pragma unroll
  for (int s = 0; s < NSPLIT; s++) M = fmaxf(M, g_Mpart[s * S_LEN + row]);
  float L = 0.0f, val = 0.0f;
#pragma unroll
  for (int s = 0; s < NSPLIT; s++) {
    const float w = __expf(g_Mpart[s * S_LEN + row] - M);
    L   += g_Lpart[s * S_LEN + row] * w;
    val += g_Opart[(s * S_LEN + row) * DOUTC + d] * w;
  }
  out[idx] = val / L;
}

// ---------------- launch ------------------------------------------------------
extern "C" void kernel_launch(void* const* d_in, const int* in_sizes, int n_in,
                              void* d_out, int out_size) {
  (void)in_sizes; (void)n_in; (void)out_size;
  const float* x  = (const float*)d_in[0];
  const float* Wq = (const float*)d_in[1];
  const float* Wk = (const float*)d_in[2];
  const float* Wv = (const float*)d_in[3];
  float* out = (float*)d_out;

  dim3 gq(S_LEN / BM, 3);
  qkv_gemm_kernel<<<gq, 256>>>(x, Wq, Wk, Wv);

  dim3 ga(S_LEN / BM, NSPLIT);
  attn_kernel<<<ga, 256>>>();

  combine_kernel<<<(S_LEN * DOUTC) / 256, 256>>>(out);
}

// round 8
// speedup vs baseline: 1.9148x; 1.9148x over previous
#include <cuda_runtime.h>
#include <cuda_fp16.h>
#include <mma.h>
#include <cstdint>

using namespace nvcuda;

#define S_LEN 8192
#define DIN   512
#define DOUTC 64
#define NSPLIT 8
#define SPLIT_KEYS (S_LEN / NSPLIT)   // 1024
#define BM 128
#define BN 64
#define SCALE 0.125f

// ---------------- scratch (device globals; no allocations allowed) ----------
__device__ __half g_Qh[S_LEN * DOUTC];
__device__ __half g_Kh[S_LEN * DOUTC];
__device__ __half g_Vh[S_LEN * DOUTC];
__device__ float  g_Opart[NSPLIT * S_LEN * DOUTC];
__device__ float  g_Lpart[NSPLIT * S_LEN];

// ---------------- QKV projection via wmma ------------------------------------
// grid (64, 3), block 256 (8 warps).  Warp w: rows [16w,16w+16) of a 128-row
// tile, all 64 output cols (4 n-tiles).  K=512 in 8 chunks of 64, fp32->fp16.
__global__ __launch_bounds__(256) void qkv_wmma_kernel(
    const float* __restrict__ x, const float* __restrict__ Wq,
    const float* __restrict__ Wk, const float* __restrict__ Wv) {
  __shared__ __half xs[128][72];   // x chunk  [m][k]
  __shared__ __half ws[64][72];    // W chunk  [n][k]  (B col_major view)
  const int tid = threadIdx.x, wid = tid >> 5, lid = tid & 31;
  const int mb = blockIdx.x * BM;
  const int sel = blockIdx.y;
  const float* W = (sel == 0) ? Wq : (sel == 1) ? Wk : Wv;
  __half* dst = (sel == 0) ? g_Qh : (sel == 1) ? g_Kh : g_Vh;

  wmma::fragment<wmma::accumulator, 16, 16, 16, float> o[4];
#pragma unroll
  for (int n = 0; n < 4; n++) wmma::fill_fragment(o[n], 0.0f);

  for (int kc = 0; kc < DIN; kc += 64) {
    __syncthreads();
    {  // xs: 128x64 floats -> half.  thread: row=tid>>1, 32 cols
      const int r = tid >> 1, c0 = (tid & 1) * 32;
      const float* src = &x[(size_t)(mb + r) * DIN + kc + c0];
#pragma unroll
      for (int j = 0; j < 8; j++) {
        float4 v = *(const float4*)(src + 4 * j);
        *(__half2*)&xs[r][c0 + 4 * j]     = __floats2half2_rn(v.x, v.y);
        *(__half2*)&xs[r][c0 + 4 * j + 2] = __floats2half2_rn(v.z, v.w);
      }
    }
    {  // ws: 64x64 floats -> half.  thread: row=tid>>2, 16 cols
      const int r = tid >> 2, c0 = (tid & 3) * 16;
      const float* src = &W[(size_t)r * DIN + kc + c0];
#pragma unroll
      for (int j = 0; j < 4; j++) {
        float4 v = *(const float4*)(src + 4 * j);
        *(__half2*)&ws[r][c0 + 4 * j]     = __floats2half2_rn(v.x, v.y);
        *(__half2*)&ws[r][c0 + 4 * j + 2] = __floats2half2_rn(v.z, v.w);
      }
    }
    __syncthreads();
#pragma unroll
    for (int n = 0; n < 4; n++) {
#pragma unroll
      for (int k = 0; k < 4; k++) {
        wmma::fragment<wmma::matrix_a, 16, 16, 16, __half, wmma::row_major> a;
        wmma::fragment<wmma::matrix_b, 16, 16, 16, __half, wmma::col_major> b;
        wmma::load_matrix_sync(a, &xs[wid * 16][k * 16], 72);
        wmma::load_matrix_sync(b, &ws[n * 16][k * 16], 72);
        wmma::mma_sync(o[n], a, b, o[n]);
      }
    }
  }

  // epilogue: stage fragments through reused smem in two warp-passes
  float* buf = (float*)&xs[0][0];             // 27.6 KB free; need 16 KB/pass
#pragma unroll
  for (int p = 0; p < 2; p++) {
    __syncthreads();
    if ((wid >> 2) == p) {
      float* st = buf + (wid & 3) * (16 * 64);
#pragma unroll
      for (int n = 0; n < 4; n++)
        wmma::store_matrix_sync(st + n * 16, o[n], 64, wmma::mem_row_major);
      __syncwarp();
      const int r = lid >> 1, c0 = (lid & 1) * 32;
      const int m = mb + wid * 16 + r;
      const float* row = st + r * 64;
#pragma unroll
      for (int j = 0; j < 16; j++)
        *(__half2*)&dst[(size_t)m * DOUTC + c0 + 2 * j] =
            __floats2half2_rn(row[c0 + 2 * j], row[c0 + 2 * j + 1]);
    }
  }
}

// ---------------- flash attention via wmma, split-KV --------------------------
// grid (64 row-blocks, NSPLIT), block 256 (8 warps).  Warp w owns 16 rows.
// Per key tile: S = Q@K^T (wmma) -> warp-private smem -> mask/exp/L -> P fp16
// -> O += P@V (wmma, persistent fragments).
#define QS_OFF 0
#define KS_OFF 18432
#define VS_OFF 27648
#define SS_OFF 36864                 // 8 warps x [16][68] f32 = 34816
#define PS_OFF 71680                 // 8 warps x [16][72] half = 18432
#define ATTN_SMEM 90112

__global__ __launch_bounds__(256) void attn_wmma_kernel() {
  const int tid = threadIdx.x, wid = tid >> 5, lid = tid & 31;
  const int row0 = blockIdx.x * BM;
  const int sp = blockIdx.y;
  const int k0 = sp * SPLIT_KEYS;
  if (k0 > row0 + BM - 1) {          // split fully masked
    if (tid < BM) g_Lpart[sp * S_LEN + row0 + tid] = 0.0f;
    return;
  }
  const int kend = min(k0 + SPLIT_KEYS, row0 + BM);

  extern __shared__ char sm[];
  __half* Qs = (__half*)(sm + QS_OFF);   // [128][72]
  __half* Ks = (__half*)(sm + KS_OFF);   // [64][72]
  __half* Vs = (__half*)(sm + VS_OFF);   // [64][72]
  float*  myS = (float*)(sm + SS_OFF) + wid * (16 * 68);
  __half* myP = (__half*)(sm + PS_OFF) + wid * (16 * 72);

  {  // Q tile load: thread: row=tid>>1, 32 halves
    const int r = tid >> 1, c0 = (tid & 1) * 32;
    const __half* src = &g_Qh[(size_t)(row0 + r) * DOUTC + c0];
#pragma unroll
    for (int j = 0; j < 4; j++)
      *(uint4*)&Qs[r * 72 + c0 + 8 * j] = *(const uint4*)(src + 8 * j);
  }
  __syncthreads();

  wmma::fragment<wmma::accumulator, 16, 16, 16, float> o[4];
#pragma unroll
  for (int n = 0; n < 4; n++) wmma::fill_fragment(o[n], 0.0f);

  const int r = lid >> 1, c0 = (lid & 1) * 32;
  const int m = row0 + wid * 16 + r;   // this lane-pair's query row
  float Lrow = 0.0f;

  for (int kb = k0; kb < kend; kb += BN) {
    __syncthreads();                   // all warps done reading Ks/Vs
    {  // K,V tiles: thread: row=tid>>2, 16 halves each
      const int rr = tid >> 2, cc = (tid & 3) * 16;
      const __half* sk = &g_Kh[(size_t)(kb + rr) * DOUTC + cc];
      const __half* sv = &g_Vh[(size_t)(kb + rr) * DOUTC + cc];
      *(uint4*)&Ks[rr * 72 + cc]     = *(const uint4*)sk;
      *(uint4*)&Ks[rr * 72 + cc + 8] = *(const uint4*)(sk + 8);
      *(uint4*)&Vs[rr * 72 + cc]     = *(const uint4*)sv;
      *(uint4*)&Vs[rr * 72 + cc + 8] = *(const uint4*)(sv + 8);
    }
    __syncthreads();

    // ---- S = Q @ K^T ----
#pragma unroll
    for (int n = 0; n < 4; n++) {
      wmma::fragment<wmma::accumulator, 16, 16, 16, float> s;
      wmma::fill_fragment(s, 0.0f);
#pragma unroll
      for (int k = 0; k < 4; k++) {
        wmma::fragment<wmma::matrix_a, 16, 16, 16, __half, wmma::row_major> a;
        wmma::fragment<wmma::matrix_b, 16, 16, 16, __half, wmma::col_major> b;
        wmma::load_matrix_sync(a, &Qs[(wid * 16) * 72 + k * 16], 72);
        wmma::load_matrix_sync(b, &Ks[(n * 16) * 72 + k * 16], 72);
        wmma::mma_sync(s, a, b, s);
      }
      wmma::store_matrix_sync(myS + n * 16, s, 68, wmma::mem_row_major);
    }
    __syncwarp();

    // ---- mask + exp + row-sum (lane pair owns one row) ----
    float ls = 0.0f;
#pragma unroll
    for (int j = 0; j < 32; j += 2) {
      const int key = kb + c0 + j;
      const float v0 = myS[r * 68 + c0 + j];
      const float v1 = myS[r * 68 + c0 + j + 1];
      const float p0 = (key     <= m) ? __expf(v0 * SCALE) : 0.0f;
      const float p1 = (key + 1 <= m) ? __expf(v1 * SCALE) : 0.0f;
      ls += p0 + p1;
      *(__half2*)&myP[r * 72 + c0 + j] = __floats2half2_rn(p0, p1);
    }
    ls += __shfl_xor_sync(0xffffffffu, ls, 1);
    Lrow += ls;
    __syncwarp();

    // ---- O += P @ V ----
#pragma unroll
    for (int n = 0; n < 4; n++) {
#pragma unroll
      for (int k = 0; k < 4; k++) {
        wmma::fragment<wmma::matrix_a, 16, 16, 16, __half, wmma::row_major> a;
        wmma::fragment<wmma::matrix_b, 16, 16, 16, __half, wmma::row_major> b;
        wmma::load_matrix_sync(a, myP + k * 16, 72);
        wmma::load_matrix_sync(b, &Vs[(k * 16) * 72 + n * 16], 72);
        wmma::mma_sync(o[n], a, b, o[n]);
      }
    }
  }

  // ---- write split partials (fragments straight to global) ----
  float* od = &g_Opart[((size_t)sp * S_LEN + row0 + wid * 16) * DOUTC];
#pragma unroll
  for (int n = 0; n < 4; n++)
    wmma::store_matrix_sync(od + n * 16, o[n], 64, wmma::mem_row_major);
  if ((lid & 1) == 0) g_Lpart[sp * S_LEN + m] = Lrow;
}

// ---------------- combine (additive: no max bookkeeping needed) --------------
__global__ __launch_bounds__(256) void combine_kernel(float* __restrict__ out) {
  const int idx = blockIdx.x * 256 + threadIdx.x;
  const int row = idx >> 6, d = idx & 63;
  float Ls = 0.0f, v = 0.0f;
#pragma unroll
  for (int sp = 0; sp < NSPLIT; sp++) {
    const float L = g_Lpart[sp * S_LEN + row];
    if (L != 0.0f) {
      Ls += L;
      v += g_Opart[((size_t)sp * S_LEN + row) * DOUTC + d];
    }
  }
  out[idx] = v / Ls;
}

// ---------------- launch ------------------------------------------------------
extern "C" void kernel_launch(void* const* d_in, const int* in_sizes, int n_in,
                              void* d_out, int out_size) {
  (void)in_sizes; (void)n_in; (void)out_size;
  const float* x  = (const float*)d_in[0];
  const float* Wq = (const float*)d_in[1];
  const float* Wk = (const float*)d_in[2];
  const float* Wv = (const float*)d_in[3];
  float* out = (float*)d_out;

  cudaFuncSetAttribute(attn_wmma_kernel,
                       cudaFuncAttributeMaxDynamicSharedMemorySize, ATTN_SMEM);

  qkv_wmma_kernel<<<dim3(S_LEN / BM, 3), 256>>>(x, Wq, Wk, Wv);
  attn_wmma_kernel<<<dim3(S_LEN / BM, NSPLIT), 256, ATTN_SMEM>>>();
  combine_kernel<<<(S_LEN * DOUTC) / 256, 256>>>(out);
}

// round 12
// speedup vs baseline: 3.4385x; 1.7958x over previous
#include <cuda_runtime.h>
#include <cuda_fp16.h>
#include <mma.h>
#include <cstdint>

using namespace nvcuda;

#define S_LEN 8192
#define DIN   512
#define DOUTC 64
#define NSPLIT 8
#define SPLIT_KEYS (S_LEN / NSPLIT)   // 1024
#define BM 128
#define BN 64
#define SCALE 0.125f

// ---------------- scratch (device globals; no allocations allowed) ----------
__device__ __half g_Qh[S_LEN * DOUTC];   // pre-scaled by 1/8 (exact in fp16)
__device__ __half g_Kh[S_LEN * DOUTC];
__device__ __half g_Vh[S_LEN * DOUTC];
__device__ float  g_Opart[NSPLIT * S_LEN * DOUTC];
__device__ float  g_Lpart[NSPLIT * S_LEN];

// ---------------- cp.async helpers ------------------------------------------
__device__ __forceinline__ uint32_t smem_u32(const void* p) {
  uint32_t a;
  asm("{ .reg .u64 t; cvta.to.shared.u64 t, %1; cvt.u32.u64 %0, t; }"
      : "=r"(a) : "l"(p));
  return a;
}
__device__ __forceinline__ void cp16(uint32_t dst, const void* src) {
  asm volatile("cp.async.cg.shared.global [%0], [%1], 16;" :: "r"(dst), "l"(src));
}
#define CP_COMMIT() asm volatile("cp.async.commit_group;" ::: "memory")
#define CP_WAIT1()  asm volatile("cp.async.wait_group 1;" ::: "memory")
#define CP_WAIT0()  asm volatile("cp.async.wait_group 0;" ::: "memory")

// ---------------- QKV projection via wmma, software-pipelined ----------------
// grid (128, 3), block 256 (8 warps).  64x64 output tile per CTA, K=512 in 8
// chunks of 64.  LDG for chunk k+1 issued before the MMAs of chunk k.
__global__ __launch_bounds__(256) void qkv_wmma_kernel(
    const float* __restrict__ x, const float* __restrict__ Wq,
    const float* __restrict__ Wk, const float* __restrict__ Wv) {
  __shared__ __align__(16) char qsm[2 * 64 * 72 * 2];   // xs + ws, 18432 B
  __half* xs = (__half*)qsm;                 // [64][72]
  __half* ws = (__half*)(qsm + 64 * 72 * 2); // [64][72]
  const int tid = threadIdx.x, wid = tid >> 5, lid = tid & 31;
  const int mb = blockIdx.x * 64;
  const int sel = blockIdx.y;
  const float* W = (sel == 0) ? Wq : (sel == 1) ? Wk : Wv;
  __half* dst = (sel == 0) ? g_Qh : (sel == 1) ? g_Kh : g_Vh;

  const int mw = wid & 3;            // m-tile (0..3)
  const int nw = (wid >> 2) * 2;     // first of two n-tiles

  wmma::fragment<wmma::accumulator, 16, 16, 16, float> o[2];
  wmma::fill_fragment(o[0], 0.0f);
  wmma::fill_fragment(o[1], 0.0f);

  const int r = tid >> 2, c0 = (tid & 3) * 16;
  const float* xp = &x[(size_t)(mb + r) * DIN + c0];
  const float* wp = &W[(size_t)r * DIN + c0];

  float4 xr[4], wr[4];
#pragma unroll
  for (int j = 0; j < 4; j++) {
    xr[j] = *(const float4*)(xp + 4 * j);
    wr[j] = *(const float4*)(wp + 4 * j);
  }

  for (int kc = 0; kc < DIN; kc += 64) {
    __syncthreads();                 // previous chunk's MMAs done; smem free
#pragma unroll
    for (int j = 0; j < 4; j++) {
      *(__half2*)&xs[r * 72 + c0 + 4 * j]     = __floats2half2_rn(xr[j].x, xr[j].y);
      *(__half2*)&xs[r * 72 + c0 + 4 * j + 2] = __floats2half2_rn(xr[j].z, xr[j].w);
      *(__half2*)&ws[r * 72 + c0 + 4 * j]     = __floats2half2_rn(wr[j].x, wr[j].y);
      *(__half2*)&ws[r * 72 + c0 + 4 * j + 2] = __floats2half2_rn(wr[j].z, wr[j].w);
    }
    __syncthreads();
    if (kc + 64 < DIN) {             // issue next chunk's LDGs; overlap w/ MMA
#pragma unroll
      for (int j = 0; j < 4; j++) {
        xr[j] = *(const float4*)(xp + kc + 64 + 4 * j);
        wr[j] = *(const float4*)(wp + kc + 64 + 4 * j);
      }
    }
#pragma unroll
    for (int k = 0; k < 4; k++) {
      wmma::fragment<wmma::matrix_a, 16, 16, 16, __half, wmma::row_major> a;
      wmma::fragment<wmma::matrix_b, 16, 16, 16, __half, wmma::col_major> b0, b1;
      wmma::load_matrix_sync(a, &xs[(mw * 16) * 72 + k * 16], 72);
      wmma::load_matrix_sync(b0, &ws[(nw * 16) * 72 + k * 16], 72);
      wmma::load_matrix_sync(b1, &ws[((nw + 1) * 16) * 72 + k * 16], 72);
      wmma::mma_sync(o[0], a, b0, o[0]);
      wmma::mma_sync(o[1], a, b1, o[1]);
    }
  }

  // epilogue: fragments -> smem fp32 -> fp16 global (scale folded for Q)
  float* buf = (float*)qsm;                        // 16384 B needed
  __syncthreads();
  wmma::store_matrix_sync(&buf[(mw * 16) * 64 + nw * 16], o[0], 64, wmma::mem_row_major);
  wmma::store_matrix_sync(&buf[(mw * 16) * 64 + nw * 16 + 16], o[1], 64, wmma::mem_row_major);
  __syncthreads();
  {
    const float s = (sel == 0) ? SCALE : 1.0f;
    const float* rp = buf + r * 64 + c0;
    __half* op = &dst[(size_t)(mb + r) * DOUTC + c0];
#pragma unroll
    for (int j = 0; j < 8; j++)
      *(__half2*)(op + 2 * j) = __floats2half2_rn(rp[2 * j] * s, rp[2 * j + 1] * s);
  }
}

// ---------------- flash attention via wmma, split-KV, cp.async prefetch ------
// grid (64 row-blocks, NSPLIT), block 256 (8 warps).  Warp w owns 16 rows.
// K/V tiles double-buffered via cp.async; per tile: S wmma -> warp-private
// smem -> mask/exp/L -> P fp16 -> O += P@V (persistent fragments).
#define KS_OFF 18432
#define VS_OFF 36864
#define SS_OFF 55296                 // 8 warps x [16][68] f32 = 34816
#define PS_OFF 90112                 // 8 warps x [16][72] half = 18432
#define ATTN_SMEM 108544
#define KVBUF 9216                   // one 64x72 fp16 tile

__global__ __launch_bounds__(256) void attn_wmma_kernel() {
  const int tid = threadIdx.x, wid = tid >> 5, lid = tid & 31;
  const int row0 = blockIdx.x * BM;
  const int sp = blockIdx.y;
  const int k0 = sp * SPLIT_KEYS;
  if (k0 > row0 + BM - 1) {          // split fully masked
    if (tid < BM) g_Lpart[sp * S_LEN + row0 + tid] = 0.0f;
    return;
  }
  const int kend = min(k0 + SPLIT_KEYS, row0 + BM);

  extern __shared__ char sm[];
  __half* Qs = (__half*)sm;                        // [128][72]
  float*  myS = (float*)(sm + SS_OFF) + wid * (16 * 68);
  __half* myP = (__half*)(sm + PS_OFF) + wid * (16 * 72);
  const uint32_t ks_u = smem_u32(sm) + KS_OFF;
  const uint32_t vs_u = smem_u32(sm) + VS_OFF;

  {  // Q tile load (once): row=tid>>1, 32 halves
    const int rr = tid >> 1, cc = (tid & 1) * 32;
    const __half* src = &g_Qh[(size_t)(row0 + rr) * DOUTC + cc];
#pragma unroll
    for (int j = 0; j < 4; j++)
      *(uint4*)&Qs[rr * 72 + cc + 8 * j] = *(const uint4*)(src + 8 * j);
  }

  // prefetch first K/V tile
  auto prefetch = [&](int buf, int kb) {
    const char* srcK = (const char*)(g_Kh + (size_t)kb * DOUTC);
    const char* srcV = (const char*)(g_Vh + (size_t)kb * DOUTC);
#pragma unroll
    for (int i = 0; i < 2; i++) {
      const int c = tid + 256 * i;
      const int rr = c >> 3, oo = (c & 7) * 16;
      cp16(ks_u + buf * KVBUF + rr * 144 + oo, srcK + rr * 128 + oo);
      cp16(vs_u + buf * KVBUF + rr * 144 + oo, srcV + rr * 128 + oo);
    }
  };
  prefetch(0, k0);
  CP_COMMIT();

  wmma::fragment<wmma::accumulator, 16, 16, 16, float> o[4];
#pragma unroll
  for (int n = 0; n < 4; n++) wmma::fill_fragment(o[n], 0.0f);

  const int r = lid >> 1, c0 = (lid & 1) * 32;
  const int m = row0 + wid * 16 + r;   // this lane-pair's query row
  float Lrow = 0.0f;
  int buf = 0;

  for (int kb = k0; kb < kend; kb += BN) {
    __syncthreads();                   // all warps done with other buffer
    if (kb + BN < kend) { prefetch(buf ^ 1, kb + BN); CP_COMMIT(); CP_WAIT1(); }
    else CP_WAIT0();
    __syncthreads();                   // cp.async data visible block-wide
    const __half* Ks = (const __half*)(sm + KS_OFF + buf * KVBUF);
    const __half* Vs = (const __half*)(sm + VS_OFF + buf * KVBUF);

    // ---- S = Q @ K^T  (Q pre-scaled by 1/8) ----
#pragma unroll
    for (int n = 0; n < 4; n++) {
      wmma::fragment<wmma::accumulator, 16, 16, 16, float> s;
      wmma::fill_fragment(s, 0.0f);
#pragma unroll
      for (int k = 0; k < 4; k++) {
        wmma::fragment<wmma::matrix_a, 16, 16, 16, __half, wmma::row_major> a;
        wmma::fragment<wmma::matrix_b, 16, 16, 16, __half, wmma::col_major> b;
        wmma::load_matrix_sync(a, &Qs[(wid * 16) * 72 + k * 16], 72);
        wmma::load_matrix_sync(b, &Ks[(n * 16) * 72 + k * 16], 72);
        wmma::mma_sync(s, a, b, s);
      }
      wmma::store_matrix_sync(myS + n * 16, s, 68, wmma::mem_row_major);
    }
    __syncwarp();

    // ---- mask + exp + row-sum (lane pair owns one row) ----
    float ls = 0.0f;
#pragma unroll
    for (int j = 0; j < 32; j += 2) {
      const int key = kb + c0 + j;
      const float v0 = myS[r * 68 + c0 + j];
      const float v1 = myS[r * 68 + c0 + j + 1];
      const float p0 = (key     <= m) ? __expf(v0) : 0.0f;
      const float p1 = (key + 1 <= m) ? __expf(v1) : 0.0f;
      ls += p0 + p1;
      *(__half2*)&myP[r * 72 + c0 + j] = __floats2half2_rn(p0, p1);
    }
    ls += __shfl_xor_sync(0xffffffffu, ls, 1);
    Lrow += ls;
    __syncwarp();

    // ---- O += P @ V ----
#pragma unroll
    for (int n = 0; n < 4; n++) {
#pragma unroll
      for (int k = 0; k < 4; k++) {
        wmma::fragment<wmma::matrix_a, 16, 16, 16, __half, wmma::row_major> a;
        wmma::fragment<wmma::matrix_b, 16, 16, 16, __half, wmma::row_major> b;
        wmma::load_matrix_sync(a, myP + k * 16, 72);
        wmma::load_matrix_sync(b, &Vs[(k * 16) * 72 + n * 16], 72);
        wmma::mma_sync(o[n], a, b, o[n]);
      }
    }
    buf ^= 1;
  }

  // ---- write split partials (fragments straight to global) ----
  float* od = &g_Opart[((size_t)sp * S_LEN + row0 + wid * 16) * DOUTC];
#pragma unroll
  for (int n = 0; n < 4; n++)
    wmma::store_matrix_sync(od + n * 16, o[n], 64, wmma::mem_row_major);
  if ((lid & 1) == 0) g_Lpart[sp * S_LEN + m] = Lrow;
}

// ---------------- combine (additive: no max bookkeeping needed) --------------
__global__ __launch_bounds__(256) void combine_kernel(float* __restrict__ out) {
  const int idx = blockIdx.x * 256 + threadIdx.x;
  const int row = idx >> 6, d = idx & 63;
  float Ls = 0.0f, v = 0.0f;
#pragma unroll
  for (int sp = 0; sp < NSPLIT; sp++) {
    const float L = g_Lpart[sp * S_LEN + row];
    if (L != 0.0f) {
      Ls += L;
      v += g_Opart[((size_t)sp * S_LEN + row) * DOUTC + d];
    }
  }
  out[idx] = v / Ls;
}

// ---------------- launch ------------------------------------------------------
extern "C" void kernel_launch(void* const* d_in, const int* in_sizes, int n_in,
                              void* d_out, int out_size) {
  (void)in_sizes; (void)n_in; (void)out_size;
  const float* x  = (const float*)d_in[0];
  const float* Wq = (const float*)d_in[1];
  const float* Wk = (const float*)d_in[2];
  const float* Wv = (const float*)d_in[3];
  float* out = (float*)d_out;

  cudaFuncSetAttribute(attn_wmma_kernel,
                       cudaFuncAttributeMaxDynamicSharedMemorySize, ATTN_SMEM);

  qkv_wmma_kernel<<<dim3(S_LEN / 64, 3), 256>>>(x, Wq, Wk, Wv);
  attn_wmma_kernel<<<dim3(S_LEN / BM, NSPLIT), 256, ATTN_SMEM>>>();
  combine_kernel<<<(S_LEN * DOUTC) / 256, 256>>>(out);
}

// round 14
// speedup vs baseline: 4.4241x; 1.2866x over previous
#include <cuda_runtime.h>
#include <cuda_fp16.h>
#include <mma.h>
#include <cstdint>

using namespace nvcuda;

#define S_LEN 8192
#define DIN   512
#define DOUTC 64
#define NSPLIT 8
#define SPLIT_KEYS (S_LEN / NSPLIT)   // 1024
#define BM 128
#define BN 64
#define SCALE 0.125f

// ---------------- scratch (device globals; no allocations allowed) ----------
__device__ __half g_Qh[S_LEN * DOUTC];   // pre-scaled by 1/8 (exact in fp16)
__device__ __half g_Kh[S_LEN * DOUTC];
__device__ __half g_Vh[S_LEN * DOUTC];
__device__ float  g_Opart[NSPLIT * S_LEN * DOUTC];
__device__ float  g_Lpart[NSPLIT * S_LEN];

// ---------------- PTX helpers ------------------------------------------------
__device__ __forceinline__ uint32_t smem_u32(const void* p) {
  uint32_t a;
  asm("{ .reg .u64 t; cvta.to.shared.u64 t, %1; cvt.u32.u64 %0, t; }"
      : "=r"(a) : "l"(p));
  return a;
}
__device__ __forceinline__ void cp16(uint32_t dst, const void* src) {
  asm volatile("cp.async.cg.shared.global [%0], [%1], 16;" :: "r"(dst), "l"(src));
}
#define CP_COMMIT() asm volatile("cp.async.commit_group;" ::: "memory")
#define CP_WAIT1()  asm volatile("cp.async.wait_group 1;" ::: "memory")
#define CP_WAIT0()  asm volatile("cp.async.wait_group 0;" ::: "memory")

__device__ __forceinline__ void ldsm4(uint32_t* r, uint32_t a) {
  asm volatile("ldmatrix.sync.aligned.m8n8.x4.shared.b16 {%0,%1,%2,%3}, [%4];"
               : "=r"(r[0]), "=r"(r[1]), "=r"(r[2]), "=r"(r[3]) : "r"(a));
}
__device__ __forceinline__ void ldsm4t(uint32_t* r, uint32_t a) {
  asm volatile("ldmatrix.sync.aligned.m8n8.x4.trans.shared.b16 {%0,%1,%2,%3}, [%4];"
               : "=r"(r[0]), "=r"(r[1]), "=r"(r[2]), "=r"(r[3]) : "r"(a));
}
// D = A(16x16) * B(16x8) + D, fp16 in / fp32 acc
__device__ __forceinline__ void mma16816(float* c, const uint32_t* a,
                                         uint32_t b0, uint32_t b1) {
  asm volatile("mma.sync.aligned.m16n8k16.row.col.f32.f16.f16.f32 "
               "{%0,%1,%2,%3}, {%4,%5,%6,%7}, {%8,%9}, {%0,%1,%2,%3};"
               : "+f"(c[0]), "+f"(c[1]), "+f"(c[2]), "+f"(c[3])
               : "r"(a[0]), "r"(a[1]), "r"(a[2]), "r"(a[3]), "r"(b0), "r"(b1));
}

// ---------------- QKV projection: cp.async fp32 staging + wmma ----------------
// grid (128, 3), block 256 (8 warps).  64x64 tile/CTA, K=512 in 8 chunks of 64.
// Chunk k+1 streams into fp32 smem via cp.async while chunk k converts + MMAs.
#define QX32(b) ((b) * 17408)            // 64 x 68 f32
#define QW32(b) (34816 + (b) * 17408)
#define QX16    69632                    // 64 x 72 f16
#define QW16    78848
#define QKV_SMEM 88064

__global__ __launch_bounds__(256) void qkv_wmma_kernel(
    const float* __restrict__ x, const float* __restrict__ Wq,
    const float* __restrict__ Wk, const float* __restrict__ Wv) {
  extern __shared__ char sm[];
  const uint32_t smu = smem_u32(sm);
  __half* xs16 = (__half*)(sm + QX16);
  __half* ws16 = (__half*)(sm + QW16);
  const int tid = threadIdx.x, wid = tid >> 5;
  const int mb = blockIdx.x * 64;
  const int sel = blockIdx.y;
  const float* W = (sel == 0) ? Wq : (sel == 1) ? Wk : Wv;
  __half* dst = (sel == 0) ? g_Qh : (sel == 1) ? g_Kh : g_Vh;

  const int mw = wid & 3, nw = (wid >> 2) * 2;
  const int cr = tid >> 2, cc0 = (tid & 3) * 16;   // convert/prefetch row, col

  auto prefetch = [&](int buf, int kc) {
#pragma unroll
    for (int i = 0; i < 4; i++) {
      const int c = tid + 256 * i, rr = c >> 4, oo = (c & 15) * 16;
      cp16(smu + QX32(buf) + rr * 272 + oo,
           (const char*)&x[(size_t)(mb + rr) * DIN + kc] + oo);
      cp16(smu + QW32(buf) + rr * 272 + oo,
           (const char*)&W[(size_t)rr * DIN + kc] + oo);
    }
  };
  prefetch(0, 0);
  CP_COMMIT();

  wmma::fragment<wmma::accumulator, 16, 16, 16, float> o[2];
  wmma::fill_fragment(o[0], 0.0f);
  wmma::fill_fragment(o[1], 0.0f);

  int buf = 0;
  for (int kc = 0; kc < DIN; kc += 64) {
    if (kc + 64 < DIN) { prefetch(buf ^ 1, kc + 64); CP_COMMIT(); CP_WAIT1(); }
    else CP_WAIT0();
    __syncthreads();                 // cp.async visible + prev MMAs done
    {  // convert fp32 stage -> fp16 tiles
      const float* xf = (const float*)(sm + QX32(buf)) + cr * 68 + cc0;
      const float* wf = (const float*)(sm + QW32(buf)) + cr * 68 + cc0;
#pragma unroll
      for (int j = 0; j < 4; j++) {
        float4 v = *(const float4*)(xf + 4 * j);
        *(__half2*)&xs16[cr * 72 + cc0 + 4 * j]     = __floats2half2_rn(v.x, v.y);
        *(__half2*)&xs16[cr * 72 + cc0 + 4 * j + 2] = __floats2half2_rn(v.z, v.w);
        float4 w = *(const float4*)(wf + 4 * j);
        *(__half2*)&ws16[cr * 72 + cc0 + 4 * j]     = __floats2half2_rn(w.x, w.y);
        *(__half2*)&ws16[cr * 72 + cc0 + 4 * j + 2] = __floats2half2_rn(w.z, w.w);
      }
    }
    __syncthreads();
#pragma unroll
    for (int k = 0; k < 4; k++) {
      wmma::fragment<wmma::matrix_a, 16, 16, 16, __half, wmma::row_major> a;
      wmma::fragment<wmma::matrix_b, 16, 16, 16, __half, wmma::col_major> b0, b1;
      wmma::load_matrix_sync(a, &xs16[(mw * 16) * 72 + k * 16], 72);
      wmma::load_matrix_sync(b0, &ws16[(nw * 16) * 72 + k * 16], 72);
      wmma::load_matrix_sync(b1, &ws16[((nw + 1) * 16) * 72 + k * 16], 72);
      wmma::mma_sync(o[0], a, b0, o[0]);
      wmma::mma_sync(o[1], a, b1, o[1]);
    }
    buf ^= 1;
  }

  // epilogue: fragments -> smem fp32 (reuse stage buf0) -> fp16 global
  float* obuf = (float*)(sm + QX32(0));
  __syncthreads();
  wmma::store_matrix_sync(&obuf[(mw * 16) * 64 + nw * 16], o[0], 64, wmma::mem_row_major);
  wmma::store_matrix_sync(&obuf[(mw * 16) * 64 + nw * 16 + 16], o[1], 64, wmma::mem_row_major);
  __syncthreads();
  {
    const float s = (sel == 0) ? SCALE : 1.0f;
    const float* rp = obuf + cr * 64 + cc0;
    __half* op = &dst[(size_t)(mb + cr) * DOUTC + cc0];
#pragma unroll
    for (int j = 0; j < 8; j++)
      *(__half2*)(op + 2 * j) = __floats2half2_rn(rp[2 * j] * s, rp[2 * j + 1] * s);
  }
}

// ---------------- flash attention: FA2 register path, mma.sync ---------------
// grid (64 row-blocks, NSPLIT), block 256 (8 warps).  Warp w: 16 query rows.
// S never leaves registers: S-frag layout == P A-frag layout for PV.
#define AKS(b) (18432 + (b) * 9216)      // K tile [64][72] f16
#define AVS(b) (36864 + (b) * 9216)      // V tile [64][72] f16
#define ATTN_SMEM 55296

__global__ __launch_bounds__(256) void attn_kernel() {
  const int tid = threadIdx.x, wid = tid >> 5, lane = tid & 31;
  const int row0 = blockIdx.x * BM;
  const int sp = blockIdx.y;
  const int k0 = sp * SPLIT_KEYS;
  if (k0 > row0 + BM - 1) {              // split fully masked
    if (tid < BM) g_Lpart[sp * S_LEN + row0 + tid] = 0.0f;
    return;
  }
  const int kend = min(k0 + SPLIT_KEYS, row0 + BM);

  extern __shared__ char sm[];
  const uint32_t smu = smem_u32(sm);
  __half* Qs = (__half*)sm;              // [128][72] staging (dead after prologue)

  auto prefetch = [&](int buf, int kb) {
    const char* srcK = (const char*)(g_Kh + (size_t)kb * DOUTC);
    const char* srcV = (const char*)(g_Vh + (size_t)kb * DOUTC);
#pragma unroll
    for (int i = 0; i < 2; i++) {
      const int c = tid + 256 * i, rr = c >> 3, oo = (c & 7) * 16;
      cp16(smu + AKS(buf) + rr * 144 + oo, srcK + rr * 128 + oo);
      cp16(smu + AVS(buf) + rr * 144 + oo, srcV + rr * 128 + oo);
    }
  };
  prefetch(0, k0);
  CP_COMMIT();

  {  // stage Q
    const int rr = tid >> 1, cc = (tid & 1) * 32;
    const __half* src = &g_Qh[(size_t)(row0 + rr) * DOUTC + cc];
#pragma unroll
    for (int j = 0; j < 4; j++)
      *(uint4*)&Qs[rr * 72 + cc + 8 * j] = *(const uint4*)(src + 8 * j);
  }
  __syncthreads();

  // Q fragments (persistent): chunk kk covers d = 16kk..16kk+15
  const int wq0 = wid * 16;
  uint32_t qf[4][4];
  {
    const uint32_t qa = smu + (wq0 + (lane & 15)) * 144 + (lane >> 4) * 16;
#pragma unroll
    for (int kk = 0; kk < 4; kk++) ldsm4(qf[kk], qa + kk * 32);
  }

  float oacc[8][4];
#pragma unroll
  for (int t = 0; t < 8; t++)
#pragma unroll
    for (int j = 0; j < 4; j++) oacc[t][j] = 0.0f;

  const int g = lane >> 2, c2 = (lane & 3) * 2;
  const int rg = row0 + wq0 + g, rg8 = rg + 8;
  float Lg = 0.0f, Lg8 = 0.0f;
  int buf = 0;

  const uint32_t koff = ((lane & 7) + ((lane >> 4) & 1) * 8) * 144 + ((lane >> 3) & 1) * 16;
  const uint32_t voff = ((lane & 7) + ((lane >> 3) & 1) * 8) * 144 + ((lane >> 4) & 1) * 16;

  for (int kb = k0; kb < kend; kb += BN) {
    __syncthreads();                   // ALL warps done reading buf^1 (prev tile)
    if (kb + BN < kend) { prefetch(buf ^ 1, kb + BN); CP_COMMIT(); CP_WAIT1(); }
    else CP_WAIT0();
    __syncthreads();                   // cp.async data visible block-wide
    const uint32_t ksb = smu + AKS(buf) + koff;
    const uint32_t vsb = smu + AVS(buf) + voff;

    // ---- S = Q @ K^T (Q pre-scaled); n-tile t covers keys kb+8t..+7 ----
    float sacc[8][4];
#pragma unroll
    for (int t = 0; t < 8; t++)
#pragma unroll
      for (int j = 0; j < 4; j++) sacc[t][j] = 0.0f;
#pragma unroll
    for (int kk = 0; kk < 4; kk++) {
#pragma unroll
      for (int np = 0; np < 4; np++) {
        uint32_t b[4];
        ldsm4(b, ksb + np * 2304 + kk * 32);
        mma16816(sacc[2 * np],     qf[kk], b[0], b[1]);
        mma16816(sacc[2 * np + 1], qf[kk], b[2], b[3]);
      }
    }

    // ---- mask + exp in registers; repack as P A-fragments ----
    uint32_t pf[4][4];
    float rs0 = 0.0f, rs1 = 0.0f;
#pragma unroll
    for (int j = 0; j < 4; j++) {   // chunk j = n-tiles 2j, 2j+1
      const int t0 = 2 * j, t1 = 2 * j + 1;
      const int ca = kb + 8 * t0 + c2, cb = kb + 8 * t1 + c2;
      float p00 = (ca     <= rg ) ? __expf(sacc[t0][0]) : 0.0f;
      float p01 = (ca + 1 <= rg ) ? __expf(sacc[t0][1]) : 0.0f;
      float p02 = (ca     <= rg8) ? __expf(sacc[t0][2]) : 0.0f;
      float p03 = (ca + 1 <= rg8) ? __expf(sacc[t0][3]) : 0.0f;
      float p10 = (cb     <= rg ) ? __expf(sacc[t1][0]) : 0.0f;
      float p11 = (cb + 1 <= rg ) ? __expf(sacc[t1][1]) : 0.0f;
      float p12 = (cb     <= rg8) ? __expf(sacc[t1][2]) : 0.0f;
      float p13 = (cb + 1 <= rg8) ? __expf(sacc[t1][3]) : 0.0f;
      rs0 += (p00 + p01) + (p10 + p11);
      rs1 += (p02 + p03) + (p12 + p13);
      __half2 h0 = __floats2half2_rn(p00, p01);
      __half2 h1 = __floats2half2_rn(p02, p03);
      __half2 h2 = __floats2half2_rn(p10, p11);
      __half2 h3 = __floats2half2_rn(p12, p13);
      pf[j][0] = reinterpret_cast<uint32_t&>(h0);
      pf[j][1] = reinterpret_cast<uint32_t&>(h1);
      pf[j][2] = reinterpret_cast<uint32_t&>(h2);
      pf[j][3] = reinterpret_cast<uint32_t&>(h3);
    }
    rs0 += __shfl_xor_sync(0xffffffffu, rs0, 1);
    rs0 += __shfl_xor_sync(0xffffffffu, rs0, 2);
    rs1 += __shfl_xor_sync(0xffffffffu, rs1, 1);
    rs1 += __shfl_xor_sync(0xffffffffu, rs1, 2);
    Lg += rs0;
    Lg8 += rs1;

    // ---- O += P @ V ----
#pragma unroll
    for (int kk = 0; kk < 4; kk++) {
#pragma unroll
      for (int np = 0; np < 4; np++) {
        uint32_t b[4];
        ldsm4t(b, vsb + kk * 2304 + np * 32);
        mma16816(oacc[2 * np],     pf[kk], b[0], b[1]);
        mma16816(oacc[2 * np + 1], pf[kk], b[2], b[3]);
      }
    }
    buf ^= 1;
  }

  // ---- write split partials ----
  float* ob = &g_Opart[((size_t)sp * S_LEN) * DOUTC];
#pragma unroll
  for (int t = 0; t < 8; t++) {
    *(float2*)&ob[(size_t)rg  * DOUTC + 8 * t + c2] = make_float2(oacc[t][0], oacc[t][1]);
    *(float2*)&ob[(size_t)rg8 * DOUTC + 8 * t + c2] = make_float2(oacc[t][2], oacc[t][3]);
  }
  if ((lane & 3) == 0) {
    g_Lpart[sp * S_LEN + rg]  = Lg;
    g_Lpart[sp * S_LEN + rg8] = Lg8;
  }
}

// ---------------- combine (additive: no max bookkeeping needed) --------------
__global__ __launch_bounds__(256) void combine_kernel(float* __restrict__ out) {
  const int idx = blockIdx.x * 256 + threadIdx.x;
  const int row = idx >> 6, d = idx & 63;
  float Ls = 0.0f, v = 0.0f;
#pragma unroll
  for (int sp = 0; sp < NSPLIT; sp++) {
    const float L = g_Lpart[sp * S_LEN + row];
    if (L != 0.0f) {
      Ls += L;
      v += g_Opart[((size_t)sp * S_LEN + row) * DOUTC + d];
    }
  }
  out[idx] = v / Ls;
}

// ---------------- launch ------------------------------------------------------
extern "C" void kernel_launch(void* const* d_in, const int* in_sizes, int n_in,
                              void* d_out, int out_size) {
  (void)in_sizes; (void)n_in; (void)out_size;
  const float* x  = (const float*)d_in[0];
  const float* Wq = (const float*)d_in[1];
  const float* Wk = (const float*)d_in[2];
  const float* Wv = (const float*)d_in[3];
  float* out = (float*)d_out;

  cudaFuncSetAttribute(qkv_wmma_kernel,
                       cudaFuncAttributeMaxDynamicSharedMemorySize, QKV_SMEM);
  cudaFuncSetAttribute(attn_kernel,
                       cudaFuncAttributeMaxDynamicSharedMemorySize, ATTN_SMEM);

  qkv_wmma_kernel<<<dim3(S_LEN / 64, 3), 256, QKV_SMEM>>>(x, Wq, Wk, Wv);
  attn_kernel<<<dim3(S_LEN / BM, NSPLIT), 256, ATTN_SMEM>>>();
  combine_kernel<<<(S_LEN * DOUTC) / 256, 256>>>(out);
}

// round 16
// speedup vs baseline: 6.0980x; 1.3784x over previous
#include <cuda_runtime.h>
#include <cuda_fp16.h>
#include <mma.h>
#include <cstdint>

using namespace nvcuda;

#define S_LEN 8192
#define DIN   512
#define DOUTC 64
#define NSPLIT 8
#define SPLIT_KEYS (S_LEN / NSPLIT)   // 1024
#define BM 128
#define BN 64
// Q pre-scale: 1/sqrt(64) * log2(e), applied in f32 before fp16 rounding
#define QSCALE 0.18033688011112042f

// ---------------- scratch (device globals; no allocations allowed) ----------
__device__ __align__(16) __half g_xh[S_LEN * DIN];        // fp16 x
__device__ __align__(16) __half g_Wh[3 * DOUTC * DIN];    // fp16 Wq|Wk|Wv
__device__ __align__(16) __half g_Qh[S_LEN * DOUTC];      // pre-scaled by QSCALE
__device__ __align__(16) __half g_Kh[S_LEN * DOUTC];
__device__ __align__(16) __half g_Vh[S_LEN * DOUTC];
__device__ float g_Opart[NSPLIT * S_LEN * DOUTC];
__device__ float g_Lpart[NSPLIT * S_LEN];

// ---------------- PTX helpers ------------------------------------------------
__device__ __forceinline__ uint32_t smem_u32(const void* p) {
  uint32_t a;
  asm("{ .reg .u64 t; cvta.to.shared.u64 t, %1; cvt.u32.u64 %0, t; }"
      : "=r"(a) : "l"(p));
  return a;
}
__device__ __forceinline__ void cp16(uint32_t dst, const void* src) {
  asm volatile("cp.async.cg.shared.global [%0], [%1], 16;" :: "r"(dst), "l"(src));
}
#define CP_COMMIT() asm volatile("cp.async.commit_group;" ::: "memory")
#define CP_WAIT1()  asm volatile("cp.async.wait_group 1;" ::: "memory")
#define CP_WAIT0()  asm volatile("cp.async.wait_group 0;" ::: "memory")

__device__ __forceinline__ void ldsm4(uint32_t* r, uint32_t a) {
  asm volatile("ldmatrix.sync.aligned.m8n8.x4.shared.b16 {%0,%1,%2,%3}, [%4];"
               : "=r"(r[0]), "=r"(r[1]), "=r"(r[2]), "=r"(r[3]) : "r"(a));
}
__device__ __forceinline__ void ldsm4t(uint32_t* r, uint32_t a) {
  asm volatile("ldmatrix.sync.aligned.m8n8.x4.trans.shared.b16 {%0,%1,%2,%3}, [%4];"
               : "=r"(r[0]), "=r"(r[1]), "=r"(r[2]), "=r"(r[3]) : "r"(a));
}
__device__ __forceinline__ void mma16816(float* c, const uint32_t* a,
                                         uint32_t b0, uint32_t b1) {
  asm volatile("mma.sync.aligned.m16n8k16.row.col.f32.f16.f16.f32 "
               "{%0,%1,%2,%3}, {%4,%5,%6,%7}, {%8,%9}, {%0,%1,%2,%3};"
               : "+f"(c[0]), "+f"(c[1]), "+f"(c[2]), "+f"(c[3])
               : "r"(a[0]), "r"(a[1]), "r"(a[2]), "r"(a[3]), "r"(b0), "r"(b1));
}
__device__ __forceinline__ float ex2(float x) {
  float y;
  asm("ex2.approx.ftz.f32 %0, %1;" : "=f"(y) : "f"(x));
  return y;
}

// ---------------- fp32 -> fp16 conversion (x and W), memory-bound ------------
// 1048 CTAs x 256 threads, 16 floats/thread over concat [x | Wq | Wk | Wv].
__global__ __launch_bounds__(256) void cvt_kernel(
    const float* __restrict__ x, const float* __restrict__ Wq,
    const float* __restrict__ Wk, const float* __restrict__ Wv) {
  const size_t i = ((size_t)blockIdx.x * 256 + threadIdx.x) * 16;
  const float* src;
  __half* dst;
  if (i < (size_t)S_LEN * DIN) {
    src = x + i;
    dst = g_xh + i;
  } else {
    size_t j = i - (size_t)S_LEN * DIN;
    if (j >= (size_t)3 * DOUTC * DIN) return;
    const int w = (int)(j >> 15);                // 32768 elems per W
    const size_t off = j & 32767;
    src = ((w == 0) ? Wq : (w == 1) ? Wk : Wv) + off;
    dst = g_Wh + j;
  }
  float4 f0 = ((const float4*)src)[0], f1 = ((const float4*)src)[1];
  float4 f2 = ((const float4*)src)[2], f3 = ((const float4*)src)[3];
  __half2 h[8] = {__floats2half2_rn(f0.x, f0.y), __floats2half2_rn(f0.z, f0.w),
                  __floats2half2_rn(f1.x, f1.y), __floats2half2_rn(f1.z, f1.w),
                  __floats2half2_rn(f2.x, f2.y), __floats2half2_rn(f2.z, f2.w),
                  __floats2half2_rn(f3.x, f3.y), __floats2half2_rn(f3.z, f3.w)};
  ((uint4*)dst)[0] = *(uint4*)&h[0];
  ((uint4*)dst)[1] = *(uint4*)&h[4];
}

// ---------------- QKV GEMM: pure fp16, cp.async double buffer ----------------
// grid (128, 3), block 256 (8 warps).  64x64 tile/CTA, K=512 in 4 chunks of
// 128.  One barrier per chunk; chunk i+1 streams while chunk i MMAs.
#define QKV_SMEM 69632                 // 2 x (x 64x136 f16 + W 64x136 f16)

__global__ __launch_bounds__(256) void qkv_gemm_kernel() {
  extern __shared__ char sm[];
  const uint32_t smu = smem_u32(sm);
  const int tid = threadIdx.x, wid = tid >> 5;
  const int mb = blockIdx.x * 64;
  const int sel = blockIdx.y;
  const __half* Wsrc = g_Wh + sel * (DOUTC * DIN);
  __half* dst = (sel == 0) ? g_Qh : (sel == 1) ? g_Kh : g_Vh;

  const int mw = wid & 3, nwg = wid >> 2;      // warp: m-tile mw, n cols nwg*32..+31

  auto prefetch = [&](int buf, int kc) {
#pragma unroll
    for (int i = 0; i < 4; i++) {
      const int c = tid + 256 * i, rr = c >> 4, cc = (c & 15) * 16;
      cp16(smu + buf * 34816 + rr * 272 + cc,
           (const char*)(g_xh + (size_t)(mb + rr) * DIN + kc) + cc);
      cp16(smu + buf * 34816 + 17408 + rr * 272 + cc,
           (const char*)(Wsrc + (size_t)rr * DIN + kc) + cc);
    }
  };
  prefetch(0, 0);
  CP_COMMIT();

  wmma::fragment<wmma::accumulator, 16, 16, 16, float> o[2];
  wmma::fill_fragment(o[0], 0.0f);
  wmma::fill_fragment(o[1], 0.0f);

  int buf = 0;
  for (int i = 0; i < 4; i++) {
    CP_WAIT0();
    __syncthreads();                 // data visible + prev MMAs done reading buf^1
    if (i < 3) prefetch(buf ^ 1, (i + 1) * 128);
    CP_COMMIT();                     // (empty group on last iter — keeps order)
    const __half* xs = (const __half*)(sm + buf * 34816);
    const __half* ws = (const __half*)(sm + buf * 34816 + 17408);
#pragma unroll
    for (int k = 0; k < 8; k++) {
      wmma::fragment<wmma::matrix_a, 16, 16, 16, __half, wmma::row_major> a;
      wmma::fragment<wmma::matrix_b, 16, 16, 16, __half, wmma::col_major> b0, b1;
      wmma::load_matrix_sync(a, &xs[(mw * 16) * 136 + k * 16], 136);
      wmma::load_matrix_sync(b0, &ws[(nwg * 32) * 136 + k * 16], 136);
      wmma::load_matrix_sync(b1, &ws[(nwg * 32 + 16) * 136 + k * 16], 136);
      wmma::mma_sync(o[0], a, b0, o[0]);
      wmma::mma_sync(o[1], a, b1, o[1]);
    }
    buf ^= 1;
  }

  // epilogue: fragments -> smem fp32 -> fp16 global (QSCALE folded for Q)
  float* obuf = (float*)sm;
  __syncthreads();
  wmma::store_matrix_sync(&obuf[(mw * 16) * 64 + nwg * 32], o[0], 64, wmma::mem_row_major);
  wmma::store_matrix_sync(&obuf[(mw * 16) * 64 + nwg * 32 + 16], o[1], 64, wmma::mem_row_major);
  __syncthreads();
  {
    const float s = (sel == 0) ? QSCALE : 1.0f;
    const int cr = tid >> 2, cc0 = (tid & 3) * 16;
    const float* rp = obuf + cr * 64 + cc0;
    __half* op = &dst[(size_t)(mb + cr) * DOUTC + cc0];
#pragma unroll
    for (int j = 0; j < 8; j++)
      *(__half2*)(op + 2 * j) = __floats2half2_rn(rp[2 * j] * s, rp[2 * j + 1] * s);
  }
}

// ---------------- flash attention: FA2 register path, 3-slot ring ------------
// grid (64 row-blocks, NSPLIT), block 256 (8 warps).  Warp w: 16 query rows.
// One barrier per key tile; S stays in registers (S-frag == P A-frag layout).
#define ASLOT(s) (18432 + (s) * 18432)   // K at +0, V at +9216 within slot
#define ATTN_SMEM 73728

__global__ __launch_bounds__(256) void attn_kernel() {
  const int tid = threadIdx.x, wid = tid >> 5, lane = tid & 31;
  const int row0 = blockIdx.x * BM;
  const int sp = blockIdx.y;
  const int k0 = sp * SPLIT_KEYS;
  if (k0 > row0 + BM - 1) {              // split fully masked
    if (tid < BM) g_Lpart[sp * S_LEN + row0 + tid] = 0.0f;
    return;
  }
  const int kend = min(k0 + SPLIT_KEYS, row0 + BM);

  extern __shared__ char sm[];
  const uint32_t smu = smem_u32(sm);
  __half* Qs = (__half*)sm;              // [128][72] staging

  auto prefetch = [&](int slot, int kb) {
    const char* srcK = (const char*)(g_Kh + (size_t)kb * DOUTC);
    const char* srcV = (const char*)(g_Vh + (size_t)kb * DOUTC);
#pragma unroll
    for (int i = 0; i < 2; i++) {
      const int c = tid + 256 * i, rr = c >> 3, oo = (c & 7) * 16;
      cp16(smu + ASLOT(slot) + rr * 144 + oo, srcK + rr * 128 + oo);
      cp16(smu + ASLOT(slot) + 9216 + rr * 144 + oo, srcV + rr * 128 + oo);
    }
  };
  prefetch(0, k0);
  CP_COMMIT();
  if (k0 + BN < kend) prefetch(1, k0 + BN);
  CP_COMMIT();                           // possibly empty — keeps group order

  {  // stage Q
    const int rr = tid >> 1, cc = (tid & 1) * 32;
    const __half* src = &g_Qh[(size_t)(row0 + rr) * DOUTC + cc];
#pragma unroll
    for (int j = 0; j < 4; j++)
      *(uint4*)&Qs[rr * 72 + cc + 8 * j] = *(const uint4*)(src + 8 * j);
  }
  __syncthreads();

  const int wq0 = wid * 16;
  uint32_t qf[4][4];                     // persistent Q fragments
  {
    const uint32_t qa = smu + (wq0 + (lane & 15)) * 144 + (lane >> 4) * 16;
#pragma unroll
    for (int kk = 0; kk < 4; kk++) ldsm4(qf[kk], qa + kk * 32);
  }

  float oacc[8][4];
#pragma unroll
  for (int t = 0; t < 8; t++)
#pragma unroll
    for (int j = 0; j < 4; j++) oacc[t][j] = 0.0f;

  const int g = lane >> 2, c2 = (lane & 3) * 2;
  const int rg = row0 + wq0 + g, rg8 = rg + 8;
  float Lg = 0.0f, Lg8 = 0.0f;
  int sl = 0;

  const uint32_t koff = ((lane & 7) + ((lane >> 4) & 1) * 8) * 144 + ((lane >> 3) & 1) * 16;
  const uint32_t voff = ((lane & 7) + ((lane >> 3) & 1) * 8) * 144 + ((lane >> 4) & 1) * 16;

  for (int kb = k0; kb < kend; kb += BN) {
    CP_WAIT1();                          // slot sl's group complete
    __syncthreads();                     // visible block-wide; slot sl+2 reads done
    {
      const int kbp = kb + 2 * BN;
      int sl2 = sl + 2; if (sl2 >= 3) sl2 -= 3;
      if (kbp < kend) prefetch(sl2, kbp);
      CP_COMMIT();                       // one group per iteration, maybe empty
    }
    const uint32_t ksb = smu + ASLOT(sl) + koff;
    const uint32_t vsb = smu + ASLOT(sl) + 9216 + voff;

    // ---- S = Q @ K^T  (log2-domain: QSCALE folded into Q) ----
    float sacc[8][4];
#pragma unroll
    for (int t = 0; t < 8; t++)
#pragma unroll
      for (int j = 0; j < 4; j++) sacc[t][j] = 0.0f;
#pragma unroll
    for (int kk = 0; kk < 4; kk++) {
#pragma unroll
      for (int np = 0; np < 4; np++) {
        uint32_t b[4];
        ldsm4(b, ksb + np * 2304 + kk * 32);
        mma16816(sacc[2 * np],     qf[kk], b[0], b[1]);
        mma16816(sacc[2 * np + 1], qf[kk], b[2], b[3]);
      }
    }

    // ---- exp2 (+ causal mask only on diagonal tiles); repack as P A-frags ----
    uint32_t pf[4][4];
    float rs0 = 0.0f, rs1 = 0.0f;
    if (kb + BN - 1 <= row0 + wq0) {     // fully unmasked for this warp
#pragma unroll
      for (int j = 0; j < 4; j++) {
        const int t0 = 2 * j, t1 = 2 * j + 1;
        float p00 = ex2(sacc[t0][0]), p01 = ex2(sacc[t0][1]);
        float p02 = ex2(sacc[t0][2]), p03 = ex2(sacc[t0][3]);
        float p10 = ex2(sacc[t1][0]), p11 = ex2(sacc[t1][1]);
        float p12 = ex2(sacc[t1][2]), p13 = ex2(sacc[t1][3]);
        rs0 += (p00 + p01) + (p10 + p11);
        rs1 += (p02 + p03) + (p12 + p13);
        __half2 h0 = __floats2half2_rn(p00, p01), h1 = __floats2half2_rn(p02, p03);
        __half2 h2 = __floats2half2_rn(p10, p11), h3 = __floats2half2_rn(p12, p13);
        pf[j][0] = reinterpret_cast<uint32_t&>(h0);
        pf[j][1] = reinterpret_cast<uint32_t&>(h1);
        pf[j][2] = reinterpret_cast<uint32_t&>(h2);
        pf[j][3] = reinterpret_cast<uint32_t&>(h3);
      }
    } else {
#pragma unroll
      for (int j = 0; j < 4; j++) {
        const int t0 = 2 * j, t1 = 2 * j + 1;
        const int ca = kb + 8 * t0 + c2, cb = kb + 8 * t1 + c2;
        float p00 = (ca     <= rg ) ? ex2(sacc[t0][0]) : 0.0f;
        float p01 = (ca + 1 <= rg ) ? ex2(sacc[t0][1]) : 0.0f;
        float p02 = (ca     <= rg8) ? ex2(sacc[t0][2]) : 0.0f;
        float p03 = (ca + 1 <= rg8) ? ex2(sacc[t0][3]) : 0.0f;
        float p10 = (cb     <= rg ) ? ex2(sacc[t1][0]) : 0.0f;
        float p11 = (cb + 1 <= rg ) ? ex2(sacc[t1][1]) : 0.0f;
        float p12 = (cb     <= rg8) ? ex2(sacc[t1][2]) : 0.0f;
        float p13 = (cb + 1 <= rg8) ? ex2(sacc[t1][3]) : 0.0f;
        rs0 += (p00 + p01) + (p10 + p11);
        rs1 += (p02 + p03) + (p12 + p13);
        __half2 h0 = __floats2half2_rn(p00, p01), h1 = __floats2half2_rn(p02, p03);
        __half2 h2 = __floats2half2_rn(p10, p11), h3 = __floats2half2_rn(p12, p13);
        pf[j][0] = reinterpret_cast<uint32_t&>(h0);
        pf[j][1] = reinterpret_cast<uint32_t&>(h1);
        pf[j][2] = reinterpret_cast<uint32_t&>(h2);
        pf[j][3] = reinterpret_cast<uint32_t&>(h3);
      }
    }
    rs0 += __shfl_xor_sync(0xffffffffu, rs0, 1);
    rs0 += __shfl_xor_sync(0xffffffffu, rs0, 2);
    rs1 += __shfl_xor_sync(0xffffffffu, rs1, 1);
    rs1 += __shfl_xor_sync(0xffffffffu, rs1, 2);
    Lg += rs0;
    Lg8 += rs1;

    // ---- O += P @ V ----
#pragma unroll
    for (int kk = 0; kk < 4; kk++) {
#pragma unroll
      for (int np = 0; np < 4; np++) {
        uint32_t b[4];
        ldsm4t(b, vsb + kk * 2304 + np * 32);
        mma16816(oacc[2 * np],     pf[kk], b[0], b[1]);
        mma16816(oacc[2 * np + 1], pf[kk], b[2], b[3]);
      }
    }
    sl++; if (sl >= 3) sl = 0;
  }

  // ---- write split partials ----
  float* ob = &g_Opart[((size_t)sp * S_LEN) * DOUTC];
#pragma unroll
  for (int t = 0; t < 8; t++) {
    *(float2*)&ob[(size_t)rg  * DOUTC + 8 * t + c2] = make_float2(oacc[t][0], oacc[t][1]);
    *(float2*)&ob[(size_t)rg8 * DOUTC + 8 * t + c2] = make_float2(oacc[t][2], oacc[t][3]);
  }
  if ((lane & 3) == 0) {
    g_Lpart[sp * S_LEN + rg]  = Lg;
    g_Lpart[sp * S_LEN + rg8] = Lg8;
  }
}

// ---------------- combine (additive: no max bookkeeping needed) --------------
__global__ __launch_bounds__(256) void combine_kernel(float* __restrict__ out) {
  const int idx = blockIdx.x * 256 + threadIdx.x;
  const int row = idx >> 6, d = idx & 63;
  float Ls = 0.0f, v = 0.0f;
#pragma unroll
  for (int sp = 0; sp < NSPLIT; sp++) {
    const float L = g_Lpart[sp * S_LEN + row];
    if (L != 0.0f) {
      Ls += L;
      v += g_Opart[((size_t)sp * S_LEN + row) * DOUTC + d];
    }
  }
  out[idx] = v / Ls;
}

// ---------------- launch ------------------------------------------------------
extern "C" void kernel_launch(void* const* d_in, const int* in_sizes, int n_in,
                              void* d_out, int out_size) {
  (void)in_sizes; (void)n_in; (void)out_size;
  const float* x  = (const float*)d_in[0];
  const float* Wq = (const float*)d_in[1];
  const float* Wk = (const float*)d_in[2];
  const float* Wv = (const float*)d_in[3];
  float* out = (float*)d_out;

  cudaFuncSetAttribute(qkv_gemm_kernel,
                       cudaFuncAttributeMaxDynamicSharedMemorySize, QKV_SMEM);
  cudaFuncSetAttribute(attn_kernel,
                       cudaFuncAttributeMaxDynamicSharedMemorySize, ATTN_SMEM);

  const int cvt_blocks = (S_LEN * DIN + 3 * DOUTC * DIN) / 16 / 256;  // 1048
  cvt_kernel<<<cvt_blocks, 256>>>(x, Wq, Wk, Wv);
  qkv_gemm_kernel<<<dim3(S_LEN / 64, 3), 256, QKV_SMEM>>>();
  attn_kernel<<<dim3(S_LEN / BM, NSPLIT), 256, ATTN_SMEM>>>();
  combine_kernel<<<(S_LEN * DOUTC) / 256, 256>>>(out);
}